// round 15
// baseline (speedup 1.0000x reference)
#include <cuda_runtime.h>

// GraphConvolution_LEGNN: out = 0.9 * rownorm1(A ⊙ same_class_mask) @ x + 0.1 * h0
// y one-hot -> mask[i][j] = (label[i]==label[j]); A ∈ {0,1}.
// Converged design: per-class column lists; each row scatters ~625 4B A-loads.
// Evidence ledger:
//   - scatter BW ceiling ~5.9TB/s; ~381MB bytes all necessary. Order/policy/
//     L1-bypass/MLP/scheduling all neutral. Streaming issue-bound (~4TB/s).
//   - R13 win: h0 load at top of drain (overlaps x-FFMA loop). main=63.4us.
// R14: FUSE prep into the main kernel. Blocks 0..39 do label+list build; all
//   blocks spin on a release/acquire flag (prep blocks are the lowest indices
//   -> first wave -> guaranteed progress). Kills the 2nd launch + gap (~2us).
//
// Inputs: d_in[0]=x [N,F] f32, d_in[1]=A [N,N] f32, d_in[2]=h0 [N,F] f32,
//         d_in[3]=y [N,C] f32.  Output: f32 [N,F].

#define N_NODES 10000
#define F_DIM   256
#define C_CLS   16
#define CAP     1024   // per-row neighbor capacity (expected ~6, worst ~40)
#define PREP_BLOCKS ((N_NODES + F_DIM - 1) / F_DIM)   // 40

__device__ int g_labels[N_NODES];
__device__ int g_ccnt[C_CLS];          // zero at load; self-reset each replay
__device__ int g_done;                 // end ticket; zero at load; self-reset
__device__ volatile int g_prep_done;   // prep-block completion count; self-reset
__device__ int g_cols[C_CLS * N_NODES];

// Single-use global load: no L1 allocation, read-only path.
__device__ __forceinline__ float ldg_noL1(const float* p) {
    float v;
    asm volatile("ld.global.nc.L1::no_allocate.f32 %0, [%1];"
                 : "=f"(v) : "l"(p));
    return v;
}

__global__ __launch_bounds__(F_DIM)
void gcn_fused_kernel(const float* __restrict__ x,
                      const float* __restrict__ A,
                      const float* __restrict__ h0,
                      const float* __restrict__ y,
                      float* __restrict__ out) {
    __shared__ int   s_idx[CAP];
    __shared__ float s_val[CAP];
    __shared__ int   s_cnt;

    const int row = blockIdx.x;
    const int tid = threadIdx.x;

    if (tid == 0) s_cnt = 0;

    // ---- Prep phase: blocks 0..39 build labels + per-class lists ----
    if (row < PREP_BLOCKS) {
        int i = row * F_DIM + tid;
        if (i < N_NODES) {
            const float* yr = y + (size_t)i * C_CLS;
            float s = 0.0f;
#pragma unroll
            for (int k = 0; k < C_CLS; ++k) s = fmaf((float)k, yr[k], s);
            int lab = __float2int_rn(s);
            g_labels[i] = lab;
            int p = atomicAdd(&g_ccnt[lab], 1);
            g_cols[lab * N_NODES + p] = i;
        }
        __threadfence();      // publish lists before the flag (release)
        __syncthreads();      // all block writes done
        if (tid == 0) atomicAdd((int*)&g_prep_done, 1);
    }

    // ---- All blocks wait until every prep block has published ----
    if (tid == 0) {
        while (g_prep_done != PREP_BLOCKS) __nanosleep(64);
    }
    __syncthreads();
    __threadfence();          // acquire: order list reads after the flag

    const int myc  = g_labels[row];
    const int ccnt = g_ccnt[myc];
    const int* __restrict__ clist = g_cols + myc * N_NODES;
    const float* __restrict__ Arow = A + (size_t)row * N_NODES;

    // ---- Gather same-class columns; A loads bypass L1 (single-use) ----
    {
        const int k0 = tid, k1 = tid + F_DIM, k2 = tid + 2 * F_DIM;
        const bool p0 = k0 < ccnt, p1 = k1 < ccnt, p2 = k2 < ccnt;
        int c0 = 0, c1 = 0, c2 = 0;
        if (p0) c0 = __ldg(&clist[k0]);
        if (p1) c1 = __ldg(&clist[k1]);
        if (p2) c2 = __ldg(&clist[k2]);
        float a0 = 0.0f, a1 = 0.0f, a2 = 0.0f;
        if (p0) a0 = ldg_noL1(&Arow[c0]);
        if (p1) a1 = ldg_noL1(&Arow[c1]);
        if (p2) a2 = ldg_noL1(&Arow[c2]);
        if (a0 != 0.0f) { int p = atomicAdd(&s_cnt, 1); if (p < CAP) { s_idx[p] = c0; s_val[p] = a0; } }
        if (a1 != 0.0f) { int p = atomicAdd(&s_cnt, 1); if (p < CAP) { s_idx[p] = c1; s_val[p] = a1; } }
        if (a2 != 0.0f) { int p = atomicAdd(&s_cnt, 1); if (p < CAP) { s_idx[p] = c2; s_val[p] = a2; } }
        // Generality tail (not taken for this distribution: ccnt ~ 625 +/- 24).
        for (int k = 3 * F_DIM + tid; k < ccnt; k += F_DIM) {
            int col  = __ldg(&clist[k]);
            float av = ldg_noL1(&Arow[col]);
            if (av != 0.0f) { int p = atomicAdd(&s_cnt, 1); if (p < CAP) { s_idx[p] = col; s_val[p] = av; } }
        }
    }
    __syncthreads();

    const int cnt = min(s_cnt, CAP);

    // ---- Drain: h0 first so its latency hides under the x-FFMA loop ----
    const size_t o = (size_t)row * F_DIM + tid;
    const float h0v = __ldcs(&h0[o]);

    float acc = 0.0f, sumw = 0.0f;
    int k = 0;
    for (; k + 4 <= cnt; k += 4) {
        int   c0 = s_idx[k],     c1 = s_idx[k + 1];
        int   c2 = s_idx[k + 2], c3 = s_idx[k + 3];
        float w0 = s_val[k],     w1 = s_val[k + 1];
        float w2 = s_val[k + 2], w3 = s_val[k + 3];
        float v0 = __ldg(&x[(size_t)c0 * F_DIM + tid]);
        float v1 = __ldg(&x[(size_t)c1 * F_DIM + tid]);
        float v2 = __ldg(&x[(size_t)c2 * F_DIM + tid]);
        float v3 = __ldg(&x[(size_t)c3 * F_DIM + tid]);
        acc  += w0 * v0 + w1 * v1 + w2 * v2 + w3 * v3;
        sumw += w0 + w1 + w2 + w3;
    }
    for (; k < cnt; ++k) {
        float w = s_val[k];
        acc  += w * __ldg(&x[(size_t)s_idx[k] * F_DIM + tid]);
        sumw += w;
    }

    float rs = fmaxf(sumw, 1e-12f);
    float res = 0.9f * (acc / rs) + 0.1f * h0v;
    __stcs(&out[o], res);   // write-once stream

    // ---- Self-reset for next graph replay ----
    // Every block's flag poll + g_ccnt/list reads precede its ticket (sync +
    // program order), so the last block's reset cannot be observed early.
    __syncthreads();
    if (tid == 0) {
        __threadfence();
        int t = atomicAdd(&g_done, 1);
        if (t == gridDim.x - 1) {
#pragma unroll
            for (int c = 0; c < C_CLS; ++c) g_ccnt[c] = 0;
            g_prep_done = 0;
            g_done = 0;
        }
    }
}

extern "C" void kernel_launch(void* const* d_in, const int* in_sizes, int n_in,
                              void* d_out, int out_size) {
    const float* x  = (const float*)d_in[0];
    const float* A  = (const float*)d_in[1];
    const float* h0 = (const float*)d_in[2];
    const float* y  = (const float*)d_in[3];
    float* out = (float*)d_out;

    gcn_fused_kernel<<<N_NODES, F_DIM>>>(x, A, h0, y, out);
}

// round 17
// speedup vs baseline: 1.1980x; 1.1980x over previous
#include <cuda_runtime.h>

// GraphConvolution_LEGNN: out = 0.9 * rownorm1(A ⊙ same_class_mask) @ x + 0.1 * h0
// y one-hot -> mask[i][j] = (label[i]==label[j]); A ∈ {0,1}.
// CONVERGED KERNEL (R13 winner, re-validated): per-class column lists; each row
// scatters ~625 4B A-loads; shared-compacted neighbor list; x-drain epilogue.
// Evidence ledger (why this is the floor):
//   - bytes: ~381MB minimum (128B-line DRAM fills over ~273 distinct lines/row;
//     data-determined, no ordering can reduce it).
//   - BW: ~5.9TB/s measured random-fill ceiling (order/policy/L1-bypass/MLP/
//     scheduling variants all neutral).
//   - dense streaming: issue-bound ~4TB/s (R1/R11). Never competitive.
//   - fusion of prep via software barrier: +13us (R14). Two launches optimal.
//   - h0 load at top of drain (R13): hides under x-FFMA loop. main=63.4us.
//
// Inputs: d_in[0]=x [N,F] f32, d_in[1]=A [N,N] f32, d_in[2]=h0 [N,F] f32,
//         d_in[3]=y [N,C] f32.  Output: f32 [N,F].

#define N_NODES 10000
#define F_DIM   256
#define C_CLS   16
#define CAP     1024   // per-row neighbor capacity (expected ~6, worst ~40)

__device__ int g_labels[N_NODES];
__device__ int g_ccnt[C_CLS];          // zero at module load; self-reset each launch
__device__ int g_done;                 // ticket; zero at load; self-reset
__device__ int g_cols[C_CLS * N_NODES];

// Single-use global load: no L1 allocation, read-only path.
__device__ __forceinline__ float ldg_noL1(const float* p) {
    float v;
    asm volatile("ld.global.nc.L1::no_allocate.f32 %0, [%1];"
                 : "=f"(v) : "l"(p));
    return v;
}

// Wide parallel prep: label from one-hot row (exact iota dot), write labels,
// atomic scatter into class list (order irrelevant).
__global__ __launch_bounds__(256)
void prep_kernel(const float* __restrict__ y) {
    int i = blockIdx.x * blockDim.x + threadIdx.x;
    if (i >= N_NODES) return;
    const float* yr = y + (size_t)i * C_CLS;
    float s = 0.0f;
#pragma unroll
    for (int k = 0; k < C_CLS; ++k) s = fmaf((float)k, yr[k], s);
    int lab = __float2int_rn(s);
    g_labels[i] = lab;
    int p = atomicAdd(&g_ccnt[lab], 1);
    g_cols[lab * N_NODES + p] = i;
}

__global__ __launch_bounds__(F_DIM)
void gcn_row_kernel(const float* __restrict__ x,
                    const float* __restrict__ A,
                    const float* __restrict__ h0,
                    float* __restrict__ out) {
    __shared__ int   s_idx[CAP];
    __shared__ float s_val[CAP];
    __shared__ int   s_cnt;

    const int row = blockIdx.x;
    const int tid = threadIdx.x;

    if (tid == 0) s_cnt = 0;
    __syncthreads();

    const int myc  = g_labels[row];
    const int ccnt = g_ccnt[myc];
    const int* __restrict__ clist = g_cols + myc * N_NODES;
    const float* __restrict__ Arow = A + (size_t)row * N_NODES;

    // Gather same-class columns; A loads bypass L1 allocation (single-use).
    // NOTHING else shares this phase's memory-queue window (R12/R14 lesson).
    {
        const int k0 = tid, k1 = tid + F_DIM, k2 = tid + 2 * F_DIM;
        const bool p0 = k0 < ccnt, p1 = k1 < ccnt, p2 = k2 < ccnt;
        int c0 = 0, c1 = 0, c2 = 0;
        if (p0) c0 = __ldg(&clist[k0]);
        if (p1) c1 = __ldg(&clist[k1]);
        if (p2) c2 = __ldg(&clist[k2]);
        float a0 = 0.0f, a1 = 0.0f, a2 = 0.0f;
        if (p0) a0 = ldg_noL1(&Arow[c0]);
        if (p1) a1 = ldg_noL1(&Arow[c1]);
        if (p2) a2 = ldg_noL1(&Arow[c2]);
        if (a0 != 0.0f) { int p = atomicAdd(&s_cnt, 1); if (p < CAP) { s_idx[p] = c0; s_val[p] = a0; } }
        if (a1 != 0.0f) { int p = atomicAdd(&s_cnt, 1); if (p < CAP) { s_idx[p] = c1; s_val[p] = a1; } }
        if (a2 != 0.0f) { int p = atomicAdd(&s_cnt, 1); if (p < CAP) { s_idx[p] = c2; s_val[p] = a2; } }
        // Generality tail (not taken for this distribution: ccnt ~ 625 +/- 24).
        for (int k = 3 * F_DIM + tid; k < ccnt; k += F_DIM) {
            int col  = __ldg(&clist[k]);
            float av = ldg_noL1(&Arow[col]);
            if (av != 0.0f) { int p = atomicAdd(&s_cnt, 1); if (p < CAP) { s_idx[p] = col; s_val[p] = av; } }
        }
    }
    __syncthreads();

    const int cnt = min(s_cnt, CAP);

    // Drain: issue h0 first so its latency hides under the x-FFMA loop.
    const size_t o = (size_t)row * F_DIM + tid;
    const float h0v = __ldcs(&h0[o]);

    float acc = 0.0f, sumw = 0.0f;
    int k = 0;
    for (; k + 4 <= cnt; k += 4) {
        int   c0 = s_idx[k],     c1 = s_idx[k + 1];
        int   c2 = s_idx[k + 2], c3 = s_idx[k + 3];
        float w0 = s_val[k],     w1 = s_val[k + 1];
        float w2 = s_val[k + 2], w3 = s_val[k + 3];
        float v0 = __ldg(&x[(size_t)c0 * F_DIM + tid]);
        float v1 = __ldg(&x[(size_t)c1 * F_DIM + tid]);
        float v2 = __ldg(&x[(size_t)c2 * F_DIM + tid]);
        float v3 = __ldg(&x[(size_t)c3 * F_DIM + tid]);
        acc  += w0 * v0 + w1 * v1 + w2 * v2 + w3 * v3;
        sumw += w0 + w1 + w2 + w3;
    }
    for (; k < cnt; ++k) {
        float w = s_val[k];
        acc  += w * __ldg(&x[(size_t)s_idx[k] * F_DIM + tid]);
        sumw += w;
    }

    float rs = fmaxf(sumw, 1e-12f);
    float res = 0.9f * (acc / rs) + 0.1f * h0v;
    __stcs(&out[o], res);   // write-once stream

    // Self-reset for next graph replay: last block zeroes the counters. This
    // block's g_ccnt reads precede the ticket (sync + program order).
    __syncthreads();
    if (tid == 0) {
        __threadfence();
        int t = atomicAdd(&g_done, 1);
        if (t == gridDim.x - 1) {
#pragma unroll
            for (int c = 0; c < C_CLS; ++c) g_ccnt[c] = 0;
            g_done = 0;
        }
    }
}

extern "C" void kernel_launch(void* const* d_in, const int* in_sizes, int n_in,
                              void* d_out, int out_size) {
    const float* x  = (const float*)d_in[0];
    const float* A  = (const float*)d_in[1];
    const float* h0 = (const float*)d_in[2];
    const float* y  = (const float*)d_in[3];
    float* out = (float*)d_out;

    prep_kernel<<<(N_NODES + 255) / 256, 256>>>(y);
    gcn_row_kernel<<<N_NODES, F_DIM>>>(x, A, h0, out);
}